// round 11
// baseline (speedup 1.0000x reference)
#include <cuda_runtime.h>

// Problem constants (fixed shapes from reference setup_inputs)
#define LNM   19
#define BSZ   2
#define HH    800
#define WW    640
#define HW    (HH * WW)            // 512000
#define NPAIR (BSZ * LNM)          // 38
#define NCHUNK 50
#define TPB   256
#define F4_PER_PLANE (HW / 4)                  // 128000
#define F4_PER_CHUNK (F4_PER_PLANE / NCHUNK)   // 2560
#define ITERS (F4_PER_CHUNK / TPB)             // 10 (exact)
#define BATCH 5
#define NMACRO (ITERS / BATCH)                 // 2
#define W4    (WW / 4)                         // 160
#define R1SQ  1681.0f              // 41*41
#define INV_R2 (1.0f / 41.0f)

#define FXSCALE 4194304.0          // 2^22
#define INV_FXSCALE (1.0 / 4194304.0)

// Deterministic cross-block accumulators: fixed-point int64 per (pair, {bce,l1x,l1y,m}).
// Main blocks contribute via fire-and-forget REDG (atomicAdd, return unused -> no
// latency on the block's critical path). Integer adds are associative -> bitwise
// deterministic. Epilogue reads+resets via atomicExch (same L2 atomic unit).
__device__ unsigned long long g_acc[NPAIR * 4];   // zero-init; reset each launch by epilogue

__global__ __launch_bounds__(TPB, 3) void loss_main_kernel(
    const float* __restrict__ fm,   // (B, 3L, H, W)
    const float* __restrict__ lmk)  // (B, L, 2)
{
    const int pair  = blockIdx.y;           // 0..37
    const int chunk = blockIdx.x;           // 0..49
    const int b = pair / LNM;
    const int l = pair % LNM;

    // Landmark center (round-half-to-even to match jnp.round)
    const float X = rintf(lmk[(b * LNM + l) * 2 + 0] * (float)(HH - 1));
    const float Y = rintf(lmk[(b * LNM + l) * 2 + 1] * (float)(WW - 1));

    // Channel base pointers as float4 streams
    const float4* __restrict__ lg =
        (const float4*)(fm + ((size_t)b * 3 * LNM + l) * (size_t)HW);
    const float4* __restrict__ px = lg + (size_t)LNM * F4_PER_PLANE;
    const float4* __restrict__ py = px + (size_t)LNM * F4_PER_PLANE;

    float s_bce = 0.0f, s_x = 0.0f, s_y = 0.0f, s_m = 0.0f;

    const int base = chunk * F4_PER_CHUNK + threadIdx.x;

    // Double-buffered register pipeline: batch mi+1's 15 LDG.128 are issued
    // BEFORE batch mi's compute, so loads stay in flight across compute.
    float4 x4[2][BATCH], px4[2][BATCH], py4[2][BATCH];

    #pragma unroll
    for (int j = 0; j < BATCH; ++j) {
        const int p4 = base + j * TPB;
        x4[0][j]  = __ldg(&lg[p4]);
        px4[0][j] = __ldg(&px[p4]);
        py4[0][j] = __ldg(&py[p4]);
    }

    #pragma unroll
    for (int mi = 0; mi < NMACRO; ++mi) {
        const int cur = mi & 1;
        // Prefetch next batch
        if (mi + 1 < NMACRO) {
            #pragma unroll
            for (int j = 0; j < BATCH; ++j) {
                const int p4 = base + ((mi + 1) * BATCH + j) * TPB;
                x4[cur ^ 1][j]  = __ldg(&lg[p4]);
                px4[cur ^ 1][j] = __ldg(&px[p4]);
                py4[cur ^ 1][j] = __ldg(&py[p4]);
            }
        }

        // Compute current batch
        #pragma unroll
        for (int j = 0; j < BATCH; ++j) {
            const int p4 = base + (mi * BATCH + j) * TPB;
            const int h  = p4 / W4;
            const int w  = (p4 - h * W4) * 4;

            const float dx   = X - (float)h;
            const float dx2  = dx * dx;
            const float offx = dx * INV_R2;

            const float xs[4]  = {x4[cur][j].x,  x4[cur][j].y,  x4[cur][j].z,  x4[cur][j].w};
            const float pxs[4] = {px4[cur][j].x, px4[cur][j].y, px4[cur][j].z, px4[cur][j].w};
            const float pys[4] = {py4[cur][j].x, py4[cur][j].y, py4[cur][j].z, py4[cur][j].w};

            #pragma unroll
            for (int k = 0; k < 4; ++k) {
                const float dy   = Y - (float)(w + k);
                const float r2   = fmaf(dy, dy, dx2);
                const float heat = (r2 <= R1SQ) ? 1.0f : 0.0f;

                // BCE-with-logits: softplus(x) - x*heat
                const float x  = xs[k];
                const float sp = fmaxf(x, 0.0f) + __logf(1.0f + __expf(-fabsf(x)));
                s_bce += sp - x * heat;

                // Masked L1 for offsets
                const float vx = fabsf(pxs[k] - offx);
                const float vy = fabsf(pys[k] - dy * INV_R2);
                s_x = fmaf(heat, vx, s_x);
                s_y = fmaf(heat, vy, s_y);
                s_m += heat;
            }
        }
    }

    // Block reduction of 4 accumulators (warp shuffle + smem)
    const unsigned FULL = 0xFFFFFFFFu;
    #pragma unroll
    for (int off = 16; off > 0; off >>= 1) {
        s_bce += __shfl_down_sync(FULL, s_bce, off);
        s_x   += __shfl_down_sync(FULL, s_x,   off);
        s_y   += __shfl_down_sync(FULL, s_y,   off);
        s_m   += __shfl_down_sync(FULL, s_m,   off);
    }

    __shared__ float smem[4][TPB / 32];
    const int lane = threadIdx.x & 31;
    const int wid  = threadIdx.x >> 5;
    if (lane == 0) {
        smem[0][wid] = s_bce;
        smem[1][wid] = s_x;
        smem[2][wid] = s_y;
        smem[3][wid] = s_m;
    }
    __syncthreads();

    if (threadIdx.x == 0) {
        float v0 = 0.0f, v1 = 0.0f, v2 = 0.0f, v3 = 0.0f;
        #pragma unroll
        for (int i = 0; i < TPB / 32; ++i) {
            v0 += smem[0][i];
            v1 += smem[1][i];
            v2 += smem[2][i];
            v3 += smem[3][i];
        }
        // Fire-and-forget fixed-point accumulation (REDG: return value unused,
        // so no latency lands on this block's critical path).
        atomicAdd(&g_acc[pair * 4 + 0],
                  (unsigned long long)(long long)llrint((double)v0 * FXSCALE));
        atomicAdd(&g_acc[pair * 4 + 1],
                  (unsigned long long)(long long)llrint((double)v1 * FXSCALE));
        atomicAdd(&g_acc[pair * 4 + 2],
                  (unsigned long long)(long long)llrint((double)v2 * FXSCALE));
        atomicAdd(&g_acc[pair * 4 + 3],
                  (unsigned long long)(long long)llrint((double)v3 * FXSCALE));
    }
}

// Epilogue (PDL secondary): cudaGridDependencySynchronize returns only after the
// primary grid fully completes, which orders all its REDG atomics before our
// reads. Reads+resets via atomicExch (L2-fresh, replay-safe).
__global__ __launch_bounds__(64) void loss_final_kernel(float* __restrict__ out)
{
#if __CUDA_ARCH__ >= 900
    cudaGridDependencySynchronize();
#endif
    const int t = threadIdx.x;
    const unsigned FULL = 0xFFFFFFFFu;

    float pl = 0.0f;
    if (t < NPAIR) {
        unsigned long long ub = atomicExch(&g_acc[t * 4 + 0], 0ull);
        unsigned long long ux = atomicExch(&g_acc[t * 4 + 1], 0ull);
        unsigned long long uy = atomicExch(&g_acc[t * 4 + 2], 0ull);
        unsigned long long um = atomicExch(&g_acc[t * 4 + 3], 0ull);
        const double sb = (double)(long long)ub * INV_FXSCALE;
        const double sx = (double)(long long)ux * INV_FXSCALE;
        const double sy = (double)(long long)uy * INV_FXSCALE;
        const double sm = (double)(long long)um * INV_FXSCALE;
        pl = (float)(2.0 * sb / (double)HW + sx / sm + sy / sm);
    }

    __shared__ float red[2];
    // Reduce 38 values: warp 0 holds pairs 0..31, warp 1 holds 32..37.
    #pragma unroll
    for (int off = 16; off > 0; off >>= 1)
        pl += __shfl_down_sync(FULL, pl, off);
    if ((t & 31) == 0) red[t >> 5] = pl;
    __syncthreads();
    if (t == 0) out[0] = (red[0] + red[1]) / (float)NPAIR;
}

extern "C" void kernel_launch(void* const* d_in, const int* in_sizes, int n_in,
                              void* d_out, int out_size)
{
    const float* fm  = (const float*)d_in[0];
    const float* lmk = (const float*)d_in[1];
    float* out = (float*)d_out;

    dim3 grid(NCHUNK, NPAIR);
    loss_main_kernel<<<grid, TPB>>>(fm, lmk);

    // Secondary launch with Programmatic Dependent Launch: overlaps the
    // epilogue's launch latency with the primary's execution. Falls back to a
    // plain serialized launch if PDL launch is unavailable.
    cudaLaunchConfig_t cfg = {};
    cfg.gridDim  = dim3(1, 1, 1);
    cfg.blockDim = dim3(64, 1, 1);
    cfg.dynamicSmemBytes = 0;
    cfg.stream = 0;
    cudaLaunchAttribute attr[1];
    attr[0].id = cudaLaunchAttributeProgrammaticStreamSerialization;
    attr[0].val.programmaticStreamSerializationAllowed = 1;
    cfg.attrs = attr;
    cfg.numAttrs = 1;
    cudaError_t err = cudaLaunchKernelEx(&cfg, loss_final_kernel, out);
    if (err != cudaSuccess) {
        loss_final_kernel<<<1, 64>>>(out);
    }
}

// round 12
// speedup vs baseline: 1.9000x; 1.9000x over previous
#include <cuda_runtime.h>

// Problem constants (fixed shapes from reference setup_inputs)
#define LNM   19
#define BSZ   2
#define HH    800
#define WW    640
#define HW    (HH * WW)            // 512000
#define NPAIR (BSZ * LNM)          // 38
#define TPB   256
#define R1I   41
#define R1SQ  1681.0f              // 41*41
#define INV_R2 (1.0f / 41.0f)

// Kernel-A (softplus stream over logits only): per batch, logits are the first
// L channels = 19*512000 floats contiguous = 2,432,000 float4.
#define A_CHUNKS 475
#define A_F4_PER_CHUNK 5120        // 2,432,000 / 475
#define A_ITERS 20                 // 5120 / 256
#define A_BATCH 5
#define A_NMACRO (A_ITERS / A_BATCH)   // 4
#define LOGITS_F4 2432000

#define FXSCALE 4194304.0          // 2^22
#define INV_FXSCALE (1.0 / 4194304.0)

// Global softplus sum, fixed-point int64 (REDG from A blocks; associative ->
// bitwise deterministic). Read+reset via atomicExch in the epilogue.
__device__ unsigned long long g_splus;
// Per-pair disc sums {sum_disc_x, l1x, l1y, msum}; one block per pair -> plain store.
__device__ float4 g_pairacc[NPAIR];

__global__ __launch_bounds__(TPB, 3) void loss_main_kernel(
    const float* __restrict__ fm,   // (B, 3L, H, W)
    const float* __restrict__ lmk)  // (B, L, 2)
{
    const unsigned FULL = 0xFFFFFFFFu;
    const int lane = threadIdx.x & 31;
    const int wid  = threadIdx.x >> 5;
    __shared__ float smem[4][TPB / 32];

    if (blockIdx.y == 2) {
        // ================= Disc blocks: one per (b,l) pair =================
        if (blockIdx.x >= NPAIR) return;
        const int pair = blockIdx.x;
        const int b = pair / LNM;
        const int l = pair % LNM;

        const float X = rintf(lmk[(b * LNM + l) * 2 + 0] * (float)(HH - 1));
        const float Y = rintf(lmk[(b * LNM + l) * 2 + 1] * (float)(WW - 1));
        const int Xi = (int)X, Yi = (int)Y;
        const int r0 = (Xi - R1I > 0) ? Xi - R1I : 0;
        const int r1 = (Xi + R1I < HH - 1) ? Xi + R1I : HH - 1;
        const int c0 = (Yi - R1I > 0) ? Yi - R1I : 0;
        const int c1 = (Yi + R1I < WW - 1) ? Yi + R1I : WW - 1;
        const int bh = r1 - r0 + 1;
        const int bw = c1 - c0 + 1;

        const float* __restrict__ lgP = fm + ((size_t)b * 3 * LNM + l) * (size_t)HW;
        const float* __restrict__ pxP = lgP + (size_t)LNM * HW;
        const float* __restrict__ pyP = pxP + (size_t)LNM * HW;

        float sD = 0.0f, sx = 0.0f, sy = 0.0f, sm = 0.0f;
        const int ncell = bh * bw;
        for (int i = threadIdx.x; i < ncell; i += TPB) {
            const int dr = i / bw;
            const int dc = i - dr * bw;
            const int h = r0 + dr;
            const int w = c0 + dc;
            const float dx = X - (float)h;
            const float dy = Y - (float)w;
            if (fmaf(dy, dy, dx * dx) <= R1SQ) {
                const int idx = h * WW + w;
                const float x = __ldg(&lgP[idx]);
                sD += x;
                sx += fabsf(__ldg(&pxP[idx]) - dx * INV_R2);
                sy += fabsf(__ldg(&pyP[idx]) - dy * INV_R2);
                sm += 1.0f;
            }
        }

        #pragma unroll
        for (int off = 16; off > 0; off >>= 1) {
            sD += __shfl_down_sync(FULL, sD, off);
            sx += __shfl_down_sync(FULL, sx, off);
            sy += __shfl_down_sync(FULL, sy, off);
            sm += __shfl_down_sync(FULL, sm, off);
        }
        if (lane == 0) {
            smem[0][wid] = sD;
            smem[1][wid] = sx;
            smem[2][wid] = sy;
            smem[3][wid] = sm;
        }
        __syncthreads();
        if (threadIdx.x == 0) {
            float v0 = 0.0f, v1 = 0.0f, v2 = 0.0f, v3 = 0.0f;
            #pragma unroll
            for (int i = 0; i < TPB / 32; ++i) {
                v0 += smem[0][i];
                v1 += smem[1][i];
                v2 += smem[2][i];
                v3 += smem[3][i];
            }
            g_pairacc[pair] = make_float4(v0, v1, v2, v3);
        }
        return;
    }

    // ============== Stream blocks: softplus sum over logits only ==============
    // Region for batch y: fm + y*3*L*HW, first L channels = LOGITS_F4 float4s.
    const float4* __restrict__ lg =
        (const float4*)(fm + (size_t)blockIdx.y * 3 * LNM * (size_t)HW);
    const int base = blockIdx.x * A_F4_PER_CHUNK + threadIdx.x;

    float s = 0.0f;

    // Double-buffered register pipeline (R8-proven): next batch's 5 LDG.128
    // issued before current batch's compute.
    float4 buf[2][A_BATCH];
    #pragma unroll
    for (int j = 0; j < A_BATCH; ++j)
        buf[0][j] = __ldg(&lg[base + j * TPB]);

    #pragma unroll
    for (int mi = 0; mi < A_NMACRO; ++mi) {
        const int cur = mi & 1;
        if (mi + 1 < A_NMACRO) {
            #pragma unroll
            for (int j = 0; j < A_BATCH; ++j)
                buf[cur ^ 1][j] = __ldg(&lg[base + ((mi + 1) * A_BATCH + j) * TPB]);
        }
        #pragma unroll
        for (int j = 0; j < A_BATCH; ++j) {
            const float xs[4] = {buf[cur][j].x, buf[cur][j].y, buf[cur][j].z, buf[cur][j].w};
            #pragma unroll
            for (int k = 0; k < 4; ++k) {
                const float x = xs[k];
                s += fmaxf(x, 0.0f) + __logf(1.0f + __expf(-fabsf(x)));
            }
        }
    }

    #pragma unroll
    for (int off = 16; off > 0; off >>= 1)
        s += __shfl_down_sync(FULL, s, off);
    if (lane == 0) smem[0][wid] = s;
    __syncthreads();
    if (threadIdx.x == 0) {
        float v = 0.0f;
        #pragma unroll
        for (int i = 0; i < TPB / 32; ++i) v += smem[0][i];
        // Fire-and-forget fixed-point accumulation (REDG: return unused).
        atomicAdd(&g_splus, (unsigned long long)(long long)llrint((double)v * FXSCALE));
    }
}

// Epilogue (PDL secondary): grid-dependency sync orders all primary writes and
// atomics before our reads.
__global__ __launch_bounds__(64) void loss_final_kernel(float* __restrict__ out)
{
#if __CUDA_ARCH__ >= 900
    cudaGridDependencySynchronize();
#endif
    const int t = threadIdx.x;
    const unsigned FULL = 0xFFFFFFFFu;

    float pl = 0.0f;   // per-pair (l1x+l1y)/m
    float pd = 0.0f;   // per-pair disc-x sum
    if (t < NPAIR) {
        const float4 v = g_pairacc[t];
        pd = v.x;
        pl = (v.y + v.z) / v.w;
    }
    #pragma unroll
    for (int off = 16; off > 0; off >>= 1) {
        pl += __shfl_down_sync(FULL, pl, off);
        pd += __shfl_down_sync(FULL, pd, off);
    }
    __shared__ float red[4];
    if ((t & 31) == 0) {
        red[(t >> 5) * 2 + 0] = pl;
        red[(t >> 5) * 2 + 1] = pd;
    }
    __syncthreads();
    if (t == 0) {
        unsigned long long uS = atomicExch(&g_splus, 0ull);   // read + reset for replay
        const double S = (double)(long long)uS * INV_FXSCALE;
        const double D = (double)(red[1] + red[3]);
        const double L1 = (double)(red[0] + red[2]);
        const double loss = 2.0 * (S - D) / ((double)NPAIR * (double)HW)
                          + L1 / (double)NPAIR;
        out[0] = (float)loss;
    }
}

extern "C" void kernel_launch(void* const* d_in, const int* in_sizes, int n_in,
                              void* d_out, int out_size)
{
    const float* fm  = (const float*)d_in[0];
    const float* lmk = (const float*)d_in[1];
    float* out = (float*)d_out;

    // y=0,1: softplus stream over batch-y logits (475 chunks each).
    // y=2:   x<38 -> disc block for pair x; others exit immediately.
    dim3 grid(A_CHUNKS, 3);
    loss_main_kernel<<<grid, TPB>>>(fm, lmk);

    // PDL epilogue; falls back to a plain launch if unavailable.
    cudaLaunchConfig_t cfg = {};
    cfg.gridDim  = dim3(1, 1, 1);
    cfg.blockDim = dim3(64, 1, 1);
    cfg.dynamicSmemBytes = 0;
    cfg.stream = 0;
    cudaLaunchAttribute attr[1];
    attr[0].id = cudaLaunchAttributeProgrammaticStreamSerialization;
    attr[0].val.programmaticStreamSerializationAllowed = 1;
    cfg.attrs = attr;
    cfg.numAttrs = 1;
    cudaError_t err = cudaLaunchKernelEx(&cfg, loss_final_kernel, out);
    if (err != cudaSuccess) {
        loss_final_kernel<<<1, 64>>>(out);
    }
}

// round 13
// speedup vs baseline: 2.5958x; 1.3662x over previous
#include <cuda_runtime.h>

// Problem constants (fixed shapes from reference setup_inputs)
#define LNM   19
#define BSZ   2
#define HH    800
#define WW    640
#define HW    (HH * WW)            // 512000
#define NPAIR (BSZ * LNM)          // 38
#define TPB   256
#define R1I   41
#define R1SQ  1681.0f              // 41*41
#define INV_R2 (1.0f / 41.0f)

// Stream work: logits = first L channels per batch = 19*512000 floats
// = 2,432,000 float4 per batch, 4,864,000 total.
// 380 stream blocks * 12800 f4/block (= 50 iters * 256 thr, exact).
#define S_BLOCKS_PER_BATCH 190
#define S_BLOCKS (2 * S_BLOCKS_PER_BATCH)      // 380
#define S_F4_PER_BLOCK 12800
#define S_ITERS 50
#define S_BATCH 5
#define S_NMACRO (S_ITERS / S_BATCH)           // 10
#define NBLOCKS (NPAIR + S_BLOCKS)             // 418 <= 148*3 slots -> single wave

#define FXSCALE 4194304.0          // 2^22
#define INV_FXSCALE (1.0 / 4194304.0)

// Global softplus sum, fixed-point int64 (REDG from stream blocks; associative ->
// bitwise deterministic). Read+reset via atomicExch in the epilogue.
__device__ unsigned long long g_splus;
// Per-pair disc sums {sum_disc_x, l1x, l1y, msum}; one block per pair -> plain store.
__device__ float4 g_pairacc[NPAIR];

__global__ __launch_bounds__(TPB, 3) void loss_main_kernel(
    const float* __restrict__ fm,   // (B, 3L, H, W)
    const float* __restrict__ lmk)  // (B, L, 2)
{
#if __CUDA_ARCH__ >= 900
    // Early PDL trigger: lets the epilogue kernel become resident NOW and spin
    // in cudaGridDependencySynchronize (which still waits for our full grid
    // completion) -> its launch latency is fully hidden.
    cudaTriggerProgrammaticLaunchCompletion();
#endif
    const unsigned FULL = 0xFFFFFFFFu;
    const int lane = threadIdx.x & 31;
    const int wid  = threadIdx.x >> 5;
    __shared__ float smem[4][TPB / 32];

    if (blockIdx.x < NPAIR) {
        // ===== Disc blocks (bid 0..37): dispatched first, overlap the stream =====
        const int pair = blockIdx.x;
        const int b = pair / LNM;
        const int l = pair % LNM;

        const float X = rintf(lmk[(b * LNM + l) * 2 + 0] * (float)(HH - 1));
        const float Y = rintf(lmk[(b * LNM + l) * 2 + 1] * (float)(WW - 1));
        const int Xi = (int)X, Yi = (int)Y;
        const int r0 = (Xi - R1I > 0) ? Xi - R1I : 0;
        const int r1 = (Xi + R1I < HH - 1) ? Xi + R1I : HH - 1;
        const int c0 = (Yi - R1I > 0) ? Yi - R1I : 0;
        const int c1 = (Yi + R1I < WW - 1) ? Yi + R1I : WW - 1;
        const int bh = r1 - r0 + 1;
        const int bw = c1 - c0 + 1;

        const float* __restrict__ lgP = fm + ((size_t)b * 3 * LNM + l) * (size_t)HW;
        const float* __restrict__ pxP = lgP + (size_t)LNM * HW;
        const float* __restrict__ pyP = pxP + (size_t)LNM * HW;

        float sD = 0.0f, sx = 0.0f, sy = 0.0f, sm = 0.0f;
        const int ncell = bh * bw;
        for (int i = threadIdx.x; i < ncell; i += TPB) {
            const int dr = i / bw;
            const int dc = i - dr * bw;
            const int h = r0 + dr;
            const int w = c0 + dc;
            const float dx = X - (float)h;
            const float dy = Y - (float)w;
            if (fmaf(dy, dy, dx * dx) <= R1SQ) {
                const int idx = h * WW + w;
                const float x = __ldg(&lgP[idx]);
                sD += x;
                sx += fabsf(__ldg(&pxP[idx]) - dx * INV_R2);
                sy += fabsf(__ldg(&pyP[idx]) - dy * INV_R2);
                sm += 1.0f;
            }
        }

        #pragma unroll
        for (int off = 16; off > 0; off >>= 1) {
            sD += __shfl_down_sync(FULL, sD, off);
            sx += __shfl_down_sync(FULL, sx, off);
            sy += __shfl_down_sync(FULL, sy, off);
            sm += __shfl_down_sync(FULL, sm, off);
        }
        if (lane == 0) {
            smem[0][wid] = sD;
            smem[1][wid] = sx;
            smem[2][wid] = sy;
            smem[3][wid] = sm;
        }
        __syncthreads();
        if (threadIdx.x == 0) {
            float v0 = 0.0f, v1 = 0.0f, v2 = 0.0f, v3 = 0.0f;
            #pragma unroll
            for (int i = 0; i < TPB / 32; ++i) {
                v0 += smem[0][i];
                v1 += smem[1][i];
                v2 += smem[2][i];
                v3 += smem[3][i];
            }
            g_pairacc[pair] = make_float4(v0, v1, v2, v3);
        }
        return;
    }

    // ===== Stream blocks: softplus sum over logits only (single wave) =====
    const int cid   = blockIdx.x - NPAIR;           // 0..379
    const int batch = cid / S_BLOCKS_PER_BATCH;     // 0..1
    const int chunk = cid % S_BLOCKS_PER_BATCH;     // 0..189

    const float4* __restrict__ lg =
        (const float4*)(fm + (size_t)batch * 3 * LNM * (size_t)HW);
    const int base = chunk * S_F4_PER_BLOCK + threadIdx.x;

    float s = 0.0f;

    // Double-buffered register pipeline: next batch's 5 LDG.128 issued before
    // current batch's compute.
    float4 buf[2][S_BATCH];
    #pragma unroll
    for (int j = 0; j < S_BATCH; ++j)
        buf[0][j] = __ldg(&lg[base + j * TPB]);

    #pragma unroll
    for (int mi = 0; mi < S_NMACRO; ++mi) {
        const int cur = mi & 1;
        if (mi + 1 < S_NMACRO) {
            #pragma unroll
            for (int j = 0; j < S_BATCH; ++j)
                buf[cur ^ 1][j] = __ldg(&lg[base + ((mi + 1) * S_BATCH + j) * TPB]);
        }
        #pragma unroll
        for (int j = 0; j < S_BATCH; ++j) {
            const float xs[4] = {buf[cur][j].x, buf[cur][j].y, buf[cur][j].z, buf[cur][j].w};
            #pragma unroll
            for (int k = 0; k < 4; ++k) {
                const float x = xs[k];
                s += fmaxf(x, 0.0f) + __logf(1.0f + __expf(-fabsf(x)));
            }
        }
    }

    #pragma unroll
    for (int off = 16; off > 0; off >>= 1)
        s += __shfl_down_sync(FULL, s, off);
    if (lane == 0) smem[0][wid] = s;
    __syncthreads();
    if (threadIdx.x == 0) {
        float v = 0.0f;
        #pragma unroll
        for (int i = 0; i < TPB / 32; ++i) v += smem[0][i];
        // Fire-and-forget fixed-point accumulation (REDG: return unused).
        atomicAdd(&g_splus, (unsigned long long)(long long)llrint((double)v * FXSCALE));
    }
}

// Epilogue (PDL secondary): resident early thanks to the primary's trigger;
// cudaGridDependencySynchronize returns once the primary grid fully completes,
// ordering all its writes/atomics before our reads.
__global__ __launch_bounds__(64) void loss_final_kernel(float* __restrict__ out)
{
#if __CUDA_ARCH__ >= 900
    cudaGridDependencySynchronize();
#endif
    const int t = threadIdx.x;
    const unsigned FULL = 0xFFFFFFFFu;

    float pl = 0.0f;   // per-pair (l1x+l1y)/m
    float pd = 0.0f;   // per-pair disc-x sum
    if (t < NPAIR) {
        const float4 v = g_pairacc[t];
        pd = v.x;
        pl = (v.y + v.z) / v.w;
    }
    #pragma unroll
    for (int off = 16; off > 0; off >>= 1) {
        pl += __shfl_down_sync(FULL, pl, off);
        pd += __shfl_down_sync(FULL, pd, off);
    }
    __shared__ float red[4];
    if ((t & 31) == 0) {
        red[(t >> 5) * 2 + 0] = pl;
        red[(t >> 5) * 2 + 1] = pd;
    }
    __syncthreads();
    if (t == 0) {
        unsigned long long uS = atomicExch(&g_splus, 0ull);   // read + reset for replay
        const double S = (double)(long long)uS * INV_FXSCALE;
        const double D = (double)(red[1] + red[3]);
        const double L1 = (double)(red[0] + red[2]);
        const double loss = 2.0 * (S - D) / ((double)NPAIR * (double)HW)
                          + L1 / (double)NPAIR;
        out[0] = (float)loss;
    }
}

extern "C" void kernel_launch(void* const* d_in, const int* in_sizes, int n_in,
                              void* d_out, int out_size)
{
    const float* fm  = (const float*)d_in[0];
    const float* lmk = (const float*)d_in[1];
    float* out = (float*)d_out;

    // Single wave: bid 0..37 disc blocks (start first, overlap), 38..417 stream.
    loss_main_kernel<<<NBLOCKS, TPB>>>(fm, lmk);

    // PDL epilogue; falls back to a plain launch if unavailable.
    cudaLaunchConfig_t cfg = {};
    cfg.gridDim  = dim3(1, 1, 1);
    cfg.blockDim = dim3(64, 1, 1);
    cfg.dynamicSmemBytes = 0;
    cfg.stream = 0;
    cudaLaunchAttribute attr[1];
    attr[0].id = cudaLaunchAttributeProgrammaticStreamSerialization;
    attr[0].val.programmaticStreamSerializationAllowed = 1;
    cfg.attrs = attr;
    cfg.numAttrs = 1;
    cudaError_t err = cudaLaunchKernelEx(&cfg, loss_final_kernel, out);
    if (err != cudaSuccess) {
        loss_final_kernel<<<1, 64>>>(out);
    }
}